// round 10
// baseline (speedup 1.0000x reference)
#include <cuda_runtime.h>
#include <math.h>

#define RUNS 512
#define WAYS 5
#define NSUP 25
#define NQ   75
#define NTOT 100
#define NEXTN 105
#define DD   640
#define EPSf 0.001f
#define LDA 114

// ---------------- device scratch (static, no allocation) ----------------
__device__ float g_proto[RUNS*WAYS*DD];
__device__ float g_addp [RUNS*WAYS*DD];
__device__ float g_M [RUNS*NEXTN*WAYS];   // sinkhorn input
__device__ float g_Z [RUNS*NEXTN*WAYS];   // Z (solve RHS path)
__device__ float g_ent[RUNS*NTOT];
__device__ float g_W [RUNS*NEXTN*NEXTN];  // graph weights
__device__ float g_sqn[RUNS*NEXTN];       // squared norms
__device__ int   g_iters;

__constant__ int TIt[10] = {0,0,0,0,1,1,1,2,2,3};
__constant__ int TJt[10] = {0,1,2,3,1,2,3,2,3,3};

// ---------------- helpers ----------------
__device__ __forceinline__ const float* frow(const float* xs, const float* xq, int b, int i) {
    if (i < NSUP) return xs + ((size_t)b*NSUP + i)*DD;
    if (i < NTOT) return xq + ((size_t)b*NQ + (i-NSUP))*DD;
    return g_addp + ((size_t)b*WAYS + (i-NTOT))*DD;
}

__device__ __forceinline__ float entropy5(const float* v) {
    float p[5]; float s = 0.f;
    #pragma unroll
    for (int k = 0; k < 5; k++) { p[k] = v[k] + 1e-12f; s += p[k]; }
    float H = 0.f;
    #pragma unroll
    for (int k = 0; k < 5; k++) { float q = p[k]/s; H -= q*logf(q); }
    return H / logf(5.0f);
}

// ---------------- proto init ----------------
__global__ void k_proto_init(const float* __restrict__ xs) {
    int b = blockIdx.x, d = threadIdx.x;
    #pragma unroll
    for (int k = 0; k < WAYS; k++) {
        float s = 0.f;
        #pragma unroll
        for (int sh = 0; sh < 5; sh++) s += xs[((size_t)b*NSUP + k*5 + sh)*DD + d];
        g_proto[((size_t)b*WAYS + k)*DD + d] = s / 5.0f;
    }
}

// ---------------- Pq + g_iters reset ----------------
__global__ void __launch_bounds__(256) k_pq(const float* __restrict__ xq) {
    int b = blockIdx.x, t = threadIdx.x;
    int w = t >> 5, lane = t & 31;
    if (b == 0 && t == 0) g_iters = 0;
    __shared__ float ps[WAYS*DD];
    __shared__ float pp[WAYS];
    const float* pr = g_proto + (size_t)b*WAYS*DD;
    for (int i = t; i < WAYS*DD/4; i += 256)
        ((float4*)ps)[i] = ((const float4*)pr)[i];
    __syncthreads();
    if (w < WAYS) {
        float s = 0.f;
        for (int d = lane; d < DD; d += 32) { float v = ps[w*DD + d]; s += v*v; }
        #pragma unroll
        for (int off = 16; off; off >>= 1) s += __shfl_xor_sync(0xffffffffu, s, off);
        if (lane == 0) pp[w] = s;
    }
    __syncthreads();
    for (int q = w; q < NQ; q += 8) {
        const float* x = xq + ((size_t)b*NQ + q)*DD;
        float dot[5] = {0,0,0,0,0}, qq = 0.f;
        for (int d = lane; d < DD; d += 32) {
            float xv = x[d];
            qq += xv*xv;
            #pragma unroll
            for (int k = 0; k < 5; k++) dot[k] += xv*ps[k*DD + d];
        }
        #pragma unroll
        for (int off = 16; off; off >>= 1) {
            qq += __shfl_xor_sync(0xffffffffu, qq, off);
            #pragma unroll
            for (int k = 0; k < 5; k++)
                dot[k] += __shfl_xor_sync(0xffffffffu, dot[k], off);
        }
        if (lane == 0) {
            #pragma unroll
            for (int k = 0; k < 5; k++) {
                float d2 = fmaxf(qq + pp[k] - 2.0f*dot[k], 0.0f);
                g_M[((size_t)b*NEXTN + q)*WAYS + k] = expf(-10.0f*d2);
            }
        }
    }
}

// ---------------- warp-resident sinkhorn ----------------
template<int N, bool CLAMP>
__device__ __forceinline__ int sink_iter(float (&P)[(N+31)/32][WAYS], int b, int lane,
                                         const int* ys, float Cval, int T) {
    const int RPT = (N+31)/32;
    float u[RPT];
    #pragma unroll
    for (int r = 0; r < RPT; r++) u[r] = 0.f;
    int K = 0;
    while (true) {
        if (T >= 0 && K >= T) break;
        float rs[RPT];
        #pragma unroll
        for (int r = 0; r < RPT; r++) {
            int row = lane + 32*r;
            rs[r] = (row < N) ? ((((P[r][0]+P[r][1])+P[r][2])+P[r][3])+P[r][4]) : 0.f;
        }
        if (T < 0) {
            float rm = 0.f;
            #pragma unroll
            for (int r = 0; r < RPT; r++) {
                int row = lane + 32*r;
                if (row < N) rm = fmaxf(rm, fabsf(u[r]-rs[r]));
            }
            #pragma unroll
            for (int off = 16; off; off >>= 1)
                rm = fmaxf(rm, __shfl_xor_sync(0xffffffffu, rm, off));
            if (rm <= EPSf || K >= 1000) break;
            #pragma unroll
            for (int r = 0; r < RPT; r++) u[r] = rs[r];
        }
        #pragma unroll
        for (int r = 0; r < RPT; r++) {
            int row = lane + 32*r;
            if (row < N) {
                float inv = 1.0f/rs[r];
                #pragma unroll
                for (int k = 0; k < WAYS; k++) P[r][k] *= inv;
            }
        }
        float cs[WAYS];
        #pragma unroll
        for (int k = 0; k < WAYS; k++) cs[k] = 0.f;
        #pragma unroll
        for (int r = 0; r < RPT; r++) {
            int row = lane + 32*r;
            if (row < N) {
                #pragma unroll
                for (int k = 0; k < WAYS; k++) cs[k] += P[r][k];
            }
        }
        #pragma unroll
        for (int off = 16; off; off >>= 1) {
            #pragma unroll
            for (int k = 0; k < WAYS; k++)
                cs[k] += __shfl_xor_sync(0xffffffffu, cs[k], off);
        }
        #pragma unroll
        for (int k = 0; k < WAYS; k++) cs[k] = Cval/cs[k];
        #pragma unroll
        for (int r = 0; r < RPT; r++) {
            int row = lane + 32*r;
            if (row < N) {
                #pragma unroll
                for (int k = 0; k < WAYS; k++) P[r][k] *= cs[k];
            }
        }
        if (CLAMP) {
            #pragma unroll
            for (int r = 0; r < RPT; r++) {
                int row = lane + 32*r;
                if (row < NSUP) {
                    int y = ys[b*NSUP + row];
                    #pragma unroll
                    for (int k = 0; k < WAYS; k++) P[r][k] = (k == y) ? 1.0f : 0.0f;
                }
            }
        }
        K++;
    }
    return K;
}

__global__ void k_sink1_count() {
    int gw = (blockIdx.x*blockDim.x + threadIdx.x) >> 5;
    int lane = threadIdx.x & 31;
    if (gw >= RUNS) return;
    float P[3][WAYS];
    const float* Mb = g_M + (size_t)gw*NEXTN*WAYS;
    #pragma unroll
    for (int r = 0; r < 3; r++) {
        int row = lane + 32*r;
        #pragma unroll
        for (int k = 0; k < WAYS; k++) P[r][k] = (row < NQ) ? Mb[row*WAYS + k] : 0.f;
    }
    int K = sink_iter<NQ, false>(P, gw, lane, nullptr, 15.0f, -1);
    if (lane == 0) atomicMax(&g_iters, K);
}

// ------- fused: sink1 replay + entropy-weighted Z + new_proto EMA -------
__global__ void __launch_bounds__(DD) k_apply_newproto(const int* __restrict__ ys,
                                                       const float* __restrict__ xs,
                                                       const float* __restrict__ xq) {
    int b = blockIdx.x, t = threadIdx.x;  // 640 threads
    int lane = t & 31;
    __shared__ float Zs[NTOT*WAYS];
    __shared__ float cs[WAYS];
    if (t < 32) {
        // warp 0: sinkhorn replay
        float P[3][WAYS];
        const float* Mb = g_M + (size_t)b*NEXTN*WAYS;
        #pragma unroll
        for (int r = 0; r < 3; r++) {
            int row = lane + 32*r;
            #pragma unroll
            for (int k = 0; k < WAYS; k++) P[r][k] = (row < NQ) ? Mb[row*WAYS + k] : 0.f;
        }
        int T = g_iters;
        sink_iter<NQ, false>(P, b, lane, nullptr, 15.0f, T);
        #pragma unroll
        for (int r = 0; r < 3; r++) {
            int row = lane + 32*r;
            if (row < NQ) {
                float e = entropy5(&P[r][0]);
                g_ent[b*NTOT + NSUP + row] = e;
                float wgt = 1.0f - e;
                #pragma unroll
                for (int k = 0; k < WAYS; k++) {
                    float zv = P[r][k]*wgt;
                    Zs[(NSUP + row)*WAYS + k] = zv;
                    g_Z[((size_t)b*NEXTN + NSUP + row)*WAYS + k] = zv;
                }
            }
        }
        if (lane < NSUP) {
            int y = ys[b*NSUP + lane];
            float v[5];
            #pragma unroll
            for (int k = 0; k < WAYS; k++) v[k] = (k == y) ? 1.0f : 0.0f;
            float e = entropy5(v);
            g_ent[b*NTOT + lane] = e;
            float wgt = 1.0f - e;
            #pragma unroll
            for (int k = 0; k < WAYS; k++) {
                float zv = v[k]*wgt;
                Zs[lane*WAYS + k] = zv;
                g_Z[((size_t)b*NEXTN + lane)*WAYS + k] = zv;
            }
        }
    }
    __syncthreads();
    if (t < WAYS) {
        float s = 0.f;
        for (int n = 0; n < NTOT; n++) s += Zs[n*WAYS + t];
        cs[t] = s;
    }
    __syncthreads();
    float acc[WAYS] = {0,0,0,0,0};
    for (int n = 0; n < NTOT; n++) {
        float f = frow(xs, xq, b, n)[t];
        #pragma unroll
        for (int k = 0; k < WAYS; k++) acc[k] += Zs[n*WAYS + k]*f;
    }
    #pragma unroll
    for (int k = 0; k < WAYS; k++) {
        size_t pi = ((size_t)b*WAYS + k)*DD + t;
        float np = acc[k]/cs[k];
        g_proto[pi] = 0.4f*g_proto[pi] + 0.6f*np;
    }
}

// ------- fused: proto mask + add_proto + Z extension + sqn -------
__global__ void __launch_bounds__(256) k_mask_sqn(const float* __restrict__ xs,
                                                  const float* __restrict__ xq) {
    int b = blockIdx.x, t = threadIdx.x;   // 256 threads
    int w = t >> 5, lane = t & 31;
    __shared__ float nrm[5], dp[5][5], score[5], mk[5], omega_s;
    const float* pr = g_proto + (size_t)b*WAYS*DD;
    if (w < 5) {
        float a = 0.f;
        for (int d = lane; d < DD; d += 32) { float v = pr[w*DD + d]; a += v*v; }
        #pragma unroll
        for (int off = 16; off; off >>= 1) a += __shfl_xor_sync(0xffffffffu, a, off);
        if (lane == 0) nrm[w] = a;
    }
    __syncthreads();
    if (w < 5) {
        for (int j = 0; j < 5; j++) {
            float s = 0.f;
            for (int d = lane; d < DD; d += 32) s += pr[w*DD + d]*pr[j*DD + d];
            #pragma unroll
            for (int off = 16; off; off >>= 1) s += __shfl_xor_sync(0xffffffffu, s, off);
            if (lane == 0) {
                float d2 = fmaxf(nrm[w] + nrm[j] - 2.0f*s, 0.0f);
                dp[w][j] = expf(-10.0f*d2);
            }
        }
    }
    __syncthreads();
    if (t < 5) score[t] = entropy5(&dp[t][0]);
    if (w == 6) {
        float s = 0.f;
        for (int i = lane; i < NTOT; i += 32) s += g_ent[b*NTOT + i];
        #pragma unroll
        for (int off = 16; off; off >>= 1) s += __shfl_xor_sync(0xffffffffu, s, off);
        if (lane == 0) omega_s = s / 100.0f;
    }
    __syncthreads();
    if (t < 5) mk[t] = (score[t] < omega_s) ? 1.0f : 0.0f;
    __syncthreads();
    for (int idx = t; idx < WAYS*DD; idx += 256) {
        int i = idx / DD, d = idx % DD;
        g_addp[((size_t)b*WAYS + i)*DD + d] = pr[i*DD + d]*mk[i];
    }
    if (t < 25) {
        int i = t / 5, k = t % 5;
        g_Z[((size_t)b*NEXTN + NTOT + i)*WAYS + k] = dp[i][k]*mk[i];
    }
    __syncthreads();   // addp (global) visible within block
    for (int row = w; row < NEXTN; row += 8) {
        const float* f = frow(xs, xq, b, row);
        float s = 0.f;
        for (int d = lane; d < DD; d += 32) { float v = f[d]; s += v*v; }
        #pragma unroll
        for (int off = 16; off; off >>= 1) s += __shfl_xor_sync(0xffffffffu, s, off);
        if (lane == 0) g_sqn[b*NEXTN + row] = s;
    }
}

// ------- 105x105 Gram -> W, kk x4 unroll with float4 smem loads -------
__global__ void __launch_bounds__(64) k_gram(const float* __restrict__ xs,
                                             const float* __restrict__ xq) {
    int b  = blockIdx.y;
    int ti = TIt[blockIdx.x], tj = TJt[blockIdx.x];
    int t  = threadIdx.x;             // 64 threads
    int tx = t & 7, ty = t >> 3;      // 8x8
    __shared__ float As[32][36], Bs[32][36];
    float acc[4][4] = {{0}};
    for (int dc = 0; dc < DD; dc += 32) {
        #pragma unroll
        for (int l = 0; l < 4; l++) {
            int id = t + l*64;              // 0..255
            int r = id >> 3, c4 = (id & 7)*4;
            int gi = ti*32 + r, gj = tj*32 + r;
            float4 av = make_float4(0,0,0,0), bv = make_float4(0,0,0,0);
            if (gi < NEXTN) av = *(const float4*)(frow(xs,xq,b,gi) + dc + c4);
            if (gj < NEXTN) bv = *(const float4*)(frow(xs,xq,b,gj) + dc + c4);
            *(float4*)&As[r][c4] = av;
            *(float4*)&Bs[r][c4] = bv;
        }
        __syncthreads();
        #pragma unroll
        for (int kk = 0; kk < 32; kk += 4) {
            float4 a4[4], b4[4];
            #pragma unroll
            for (int i = 0; i < 4; i++) a4[i] = *(const float4*)&As[ty*4+i][kk];
            #pragma unroll
            for (int j = 0; j < 4; j++) b4[j] = *(const float4*)&Bs[tx*4+j][kk];
            #pragma unroll
            for (int i = 0; i < 4; i++)
                #pragma unroll
                for (int j = 0; j < 4; j++)
                    acc[i][j] += a4[i].x*b4[j].x + a4[i].y*b4[j].y
                               + a4[i].z*b4[j].z + a4[i].w*b4[j].w;
        }
        __syncthreads();
    }
    size_t Wb = (size_t)b*NEXTN*NEXTN;
    #pragma unroll
    for (int ii = 0; ii < 4; ii++)
    #pragma unroll
    for (int jj = 0; jj < 4; jj++) {
        int i = ti*32 + ty*4 + ii, j = tj*32 + tx*4 + jj;
        if (i < NEXTN && j < NEXTN) {
            float d2 = g_sqn[b*NEXTN + i] + g_sqn[b*NEXTN + j] - 2.0f*acc[ii][jj];
            d2 = fmaxf(d2, 0.0f);
            float wv = (i == j) ? 0.0f : expf(-10.0f*d2);
            g_W[Wb + (size_t)i*NEXTN + j] = wv;
            if (ti != tj) g_W[Wb + (size_t)j*NEXTN + i] = wv;
        }
    }
}

// ------- solve (I - 0.7 * Dm W Dm) X = Z -> g_M  (+ g_iters reset) -------
__global__ void __launch_bounds__(128) k_solve() {
    int b = blockIdx.x, t = threadIdx.x;
    if (b == 0 && t == 0) g_iters = 0;
    __shared__ float A[NEXTN*LDA];
    __shared__ float dm[NEXTN];
    const float* Wb = g_W + (size_t)b*NEXTN*NEXTN;
    for (int idx = t; idx < NEXTN*NEXTN; idx += 128) {
        int i = idx/NEXTN, j = idx%NEXTN;
        A[i*LDA + j] = Wb[idx];
    }
    __syncthreads();
    if (t < NEXTN) {
        float s = 0.f;
        for (int j = 0; j < NEXTN; j++) s += A[t*LDA + j];
        dm[t] = rsqrtf(s);
    }
    __syncthreads();
    if (t < NEXTN) {
        float di = 0.7f*dm[t];
        for (int j = 0; j < NEXTN; j++) {
            float v = di*dm[j]*A[t*LDA + j];
            A[t*LDA + j] = ((t == j) ? 1.0f : 0.0f) - v;
        }
        #pragma unroll
        for (int k = 0; k < WAYS; k++)
            A[t*LDA + NEXTN + k] = g_Z[((size_t)b*NEXTN + t)*WAYS + k];
    }
    __syncthreads();
    for (int k = 0; k < NEXTN; k++) {
        if (t < NEXTN && t != k) {
            float f = A[t*LDA + k] / A[k*LDA + k];
            int j = k + 1;
            if (j & 1) { A[t*LDA + j] -= f*A[k*LDA + j]; j++; }
            for (; j < NEXTN + WAYS; j += 2) {
                float2 pv = *(const float2*)&A[k*LDA + j];
                float2 av = *(float2*)&A[t*LDA + j];
                av.x -= f*pv.x; av.y -= f*pv.y;
                *(float2*)&A[t*LDA + j] = av;
            }
        }
        __syncthreads();
    }
    if (t < NEXTN) {
        float inv = 1.0f / A[t*LDA + t];
        #pragma unroll
        for (int k = 0; k < WAYS; k++)
            g_M[((size_t)b*NEXTN + t)*WAYS + k] = A[t*LDA + NEXTN + k]*inv;
    }
}

__global__ void k_sink2_count(const int* __restrict__ ys) {
    int gw = (blockIdx.x*blockDim.x + threadIdx.x) >> 5;
    int lane = threadIdx.x & 31;
    if (gw >= RUNS) return;
    float P[4][WAYS];
    const float* Mb = g_M + (size_t)gw*NEXTN*WAYS;
    #pragma unroll
    for (int r = 0; r < 4; r++) {
        int row = lane + 32*r;
        #pragma unroll
        for (int k = 0; k < WAYS; k++) P[r][k] = (row < NEXTN) ? Mb[row*WAYS + k] : 0.f;
    }
    int K = sink_iter<NEXTN, true>(P, gw, lane, ys, 21.0f, -1);
    if (lane == 0) atomicMax(&g_iters, K);
}

// ------- fused: sink2 replay + argmax predict -------
__global__ void k_sink2_pred(const int* __restrict__ ys, const int* __restrict__ yq,
                             float* __restrict__ out) {
    int gw = (blockIdx.x*blockDim.x + threadIdx.x) >> 5;
    int lane = threadIdx.x & 31;
    if (gw >= RUNS) return;
    int b = gw;
    float P[4][WAYS];
    const float* Mb = g_M + (size_t)b*NEXTN*WAYS;
    #pragma unroll
    for (int r = 0; r < 4; r++) {
        int row = lane + 32*r;
        #pragma unroll
        for (int k = 0; k < WAYS; k++) P[r][k] = (row < NEXTN) ? Mb[row*WAYS + k] : 0.f;
    }
    int T = g_iters;
    sink_iter<NEXTN, true>(P, b, lane, ys, 21.0f, T);
    int cnt = 0;
    #pragma unroll
    for (int r = 0; r < 4; r++) {
        int row = lane + 32*r;
        if (row >= NSUP && row < NTOT) {
            int am = 0; float bv = P[r][0];
            #pragma unroll
            for (int k = 1; k < 5; k++) { float v = P[r][k]; if (v > bv) { bv = v; am = k; } }
            cnt += (am == yq[b*NQ + (row - NSUP)]) ? 1 : 0;
        }
    }
    #pragma unroll
    for (int off = 16; off; off >>= 1) cnt += __shfl_xor_sync(0xffffffffu, cnt, off);
    if (lane == 0) out[b] = (float)cnt / 75.0f;
}

extern "C" void kernel_launch(void* const* d_in, const int* in_sizes, int n_in,
                              void* d_out, int out_size) {
    const float* xs = (const float*)d_in[0];
    const float* xq = (const float*)d_in[1];
    const int*   ys = (const int*)d_in[2];
    const int*   yq = (const int*)d_in[3];
    float* out = (float*)d_out;

    k_proto_init<<<RUNS, DD>>>(xs);
    for (int e = 0; e < 3; e++) {
        k_pq<<<RUNS, 256>>>(xq);
        k_sink1_count<<<(RUNS*32 + 255)/256, 256>>>();
        k_apply_newproto<<<RUNS, DD>>>(ys, xs, xq);
        if (e == 2) {
            k_mask_sqn<<<RUNS, 256>>>(xs, xq);
            k_gram<<<dim3(10, RUNS), 64>>>(xs, xq);
            k_solve<<<RUNS, 128>>>();
            k_sink2_count<<<(RUNS*32 + 255)/256, 256>>>(ys);
            k_sink2_pred<<<(RUNS*32 + 255)/256, 256>>>(ys, yq, out);
        }
    }
}

// round 14
// speedup vs baseline: 1.1081x; 1.1081x over previous
#include <cuda_runtime.h>
#include <math.h>

#define RUNS 512
#define WAYS 5
#define NSUP 25
#define NQ   75
#define NTOT 100
#define NEXTN 105
#define DD   640
#define EPSf 0.001f
#define LDA 114

// ---------------- device scratch (static, no allocation) ----------------
__device__ float g_proto[RUNS*WAYS*DD];
__device__ float g_addp [RUNS*WAYS*DD];
__device__ float g_M [RUNS*NEXTN*WAYS];   // sinkhorn input
__device__ float g_Z [RUNS*NEXTN*WAYS];   // Z (solve RHS path)
__device__ float g_ent[RUNS*NTOT];
__device__ float g_W [RUNS*NEXTN*NEXTN];  // graph weights
__device__ float g_sqn[RUNS*NEXTN];       // squared norms
__device__ int   g_it1[3];                // per-epoch sink1 iters
__device__ int   g_it2;                   // sink2 iters

__constant__ int TIt[10] = {0,0,0,0,1,1,1,2,2,3};
__constant__ int TJt[10] = {0,1,2,3,1,2,3,2,3,3};

// ---------------- helpers ----------------
__device__ __forceinline__ const float* frow(const float* xs, const float* xq, int b, int i) {
    if (i < NSUP) return xs + ((size_t)b*NSUP + i)*DD;
    if (i < NTOT) return xq + ((size_t)b*NQ + (i-NSUP))*DD;
    return g_addp + ((size_t)b*WAYS + (i-NTOT))*DD;
}

__device__ __forceinline__ float entropy5(const float* v) {
    float p[5]; float s = 0.f;
    #pragma unroll
    for (int k = 0; k < 5; k++) { p[k] = v[k] + 1e-12f; s += p[k]; }
    float H = 0.f;
    #pragma unroll
    for (int k = 0; k < 5; k++) { float q = p[k]/s; H -= q*logf(q); }
    return H / logf(5.0f);
}

// ---------------- proto init + counter resets ----------------
__global__ void k_proto_init(const float* __restrict__ xs) {
    int b = blockIdx.x, d = threadIdx.x;
    if (b == 0 && d == 0) { g_it1[0] = 0; g_it1[1] = 0; g_it1[2] = 0; g_it2 = 0; }
    #pragma unroll
    for (int k = 0; k < WAYS; k++) {
        float s = 0.f;
        #pragma unroll
        for (int sh = 0; sh < 5; sh++) s += xs[((size_t)b*NSUP + k*5 + sh)*DD + d];
        g_proto[((size_t)b*WAYS + k)*DD + d] = s / 5.0f;
    }
}

// ---------------- warp-resident sinkhorn ----------------
template<int N, bool CLAMP>
__device__ __forceinline__ int sink_iter(float (&P)[(N+31)/32][WAYS], int b, int lane,
                                         const int* ys, float Cval, int T) {
    const int RPT = (N+31)/32;
    float u[RPT];
    #pragma unroll
    for (int r = 0; r < RPT; r++) u[r] = 0.f;
    int K = 0;
    while (true) {
        if (T >= 0 && K >= T) break;
        float rs[RPT];
        #pragma unroll
        for (int r = 0; r < RPT; r++) {
            int row = lane + 32*r;
            rs[r] = (row < N) ? ((((P[r][0]+P[r][1])+P[r][2])+P[r][3])+P[r][4]) : 0.f;
        }
        if (T < 0) {
            float rm = 0.f;
            #pragma unroll
            for (int r = 0; r < RPT; r++) {
                int row = lane + 32*r;
                if (row < N) rm = fmaxf(rm, fabsf(u[r]-rs[r]));
            }
            #pragma unroll
            for (int off = 16; off; off >>= 1)
                rm = fmaxf(rm, __shfl_xor_sync(0xffffffffu, rm, off));
            if (rm <= EPSf || K >= 1000) break;
            #pragma unroll
            for (int r = 0; r < RPT; r++) u[r] = rs[r];
        }
        #pragma unroll
        for (int r = 0; r < RPT; r++) {
            int row = lane + 32*r;
            if (row < N) {
                float inv = 1.0f/rs[r];
                #pragma unroll
                for (int k = 0; k < WAYS; k++) P[r][k] *= inv;
            }
        }
        float cs[WAYS];
        #pragma unroll
        for (int k = 0; k < WAYS; k++) cs[k] = 0.f;
        #pragma unroll
        for (int r = 0; r < RPT; r++) {
            int row = lane + 32*r;
            if (row < N) {
                #pragma unroll
                for (int k = 0; k < WAYS; k++) cs[k] += P[r][k];
            }
        }
        #pragma unroll
        for (int off = 16; off; off >>= 1) {
            #pragma unroll
            for (int k = 0; k < WAYS; k++)
                cs[k] += __shfl_xor_sync(0xffffffffu, cs[k], off);
        }
        #pragma unroll
        for (int k = 0; k < WAYS; k++) cs[k] = Cval/cs[k];
        #pragma unroll
        for (int r = 0; r < RPT; r++) {
            int row = lane + 32*r;
            if (row < N) {
                #pragma unroll
                for (int k = 0; k < WAYS; k++) P[r][k] *= cs[k];
            }
        }
        if (CLAMP) {
            #pragma unroll
            for (int r = 0; r < RPT; r++) {
                int row = lane + 32*r;
                if (row < NSUP) {
                    int y = ys[b*NSUP + row];
                    #pragma unroll
                    for (int k = 0; k < WAYS; k++) P[r][k] = (k == y) ? 1.0f : 0.0f;
                }
            }
        }
        K++;
    }
    return K;
}

// ------- fused: Pq + sink1 count (per-epoch counter) -------
__global__ void __launch_bounds__(256) k_pq_count(const float* __restrict__ xq, int e) {
    int b = blockIdx.x, t = threadIdx.x;
    int w = t >> 5, lane = t & 31;
    __shared__ float ps[WAYS*DD];
    __shared__ float pp[WAYS];
    __shared__ float Ms[NQ*WAYS];
    const float* pr = g_proto + (size_t)b*WAYS*DD;
    for (int i = t; i < WAYS*DD/4; i += 256)
        ((float4*)ps)[i] = ((const float4*)pr)[i];
    __syncthreads();
    if (w < WAYS) {
        float s = 0.f;
        for (int d = lane; d < DD; d += 32) { float v = ps[w*DD + d]; s += v*v; }
        #pragma unroll
        for (int off = 16; off; off >>= 1) s += __shfl_xor_sync(0xffffffffu, s, off);
        if (lane == 0) pp[w] = s;
    }
    __syncthreads();
    for (int q = w; q < NQ; q += 8) {
        const float* x = xq + ((size_t)b*NQ + q)*DD;
        float dot[5] = {0,0,0,0,0}, qq = 0.f;
        for (int d = lane; d < DD; d += 32) {
            float xv = x[d];
            qq += xv*xv;
            #pragma unroll
            for (int k = 0; k < 5; k++) dot[k] += xv*ps[k*DD + d];
        }
        #pragma unroll
        for (int off = 16; off; off >>= 1) {
            qq += __shfl_xor_sync(0xffffffffu, qq, off);
            #pragma unroll
            for (int k = 0; k < 5; k++)
                dot[k] += __shfl_xor_sync(0xffffffffu, dot[k], off);
        }
        if (lane == 0) {
            #pragma unroll
            for (int k = 0; k < 5; k++) {
                float d2 = fmaxf(qq + pp[k] - 2.0f*dot[k], 0.0f);
                float m = expf(-10.0f*d2);
                Ms[q*WAYS + k] = m;
                g_M[((size_t)b*NEXTN + q)*WAYS + k] = m;
            }
        }
    }
    __syncthreads();
    if (t < 32) {
        float P[3][WAYS];
        #pragma unroll
        for (int r = 0; r < 3; r++) {
            int row = lane + 32*r;
            #pragma unroll
            for (int k = 0; k < WAYS; k++) P[r][k] = (row < NQ) ? Ms[row*WAYS + k] : 0.f;
        }
        int K = sink_iter<NQ, false>(P, b, lane, nullptr, 15.0f, -1);
        if (lane == 0) atomicMax(&g_it1[e], K);
    }
}

// ------- fused: sink1 replay + entropy-weighted Z + new_proto EMA -------
__global__ void __launch_bounds__(DD) k_apply_newproto(const int* __restrict__ ys,
                                                       const float* __restrict__ xs,
                                                       const float* __restrict__ xq,
                                                       int e) {
    int b = blockIdx.x, t = threadIdx.x;  // 640 threads
    int lane = t & 31;
    __shared__ float Zs[NTOT*WAYS];
    __shared__ float cs[WAYS];
    if (t < 32) {
        float P[3][WAYS];
        const float* Mb = g_M + (size_t)b*NEXTN*WAYS;
        #pragma unroll
        for (int r = 0; r < 3; r++) {
            int row = lane + 32*r;
            #pragma unroll
            for (int k = 0; k < WAYS; k++) P[r][k] = (row < NQ) ? Mb[row*WAYS + k] : 0.f;
        }
        int T = g_it1[e];
        sink_iter<NQ, false>(P, b, lane, nullptr, 15.0f, T);
        #pragma unroll
        for (int r = 0; r < 3; r++) {
            int row = lane + 32*r;
            if (row < NQ) {
                float e2 = entropy5(&P[r][0]);
                g_ent[b*NTOT + NSUP + row] = e2;
                float wgt = 1.0f - e2;
                #pragma unroll
                for (int k = 0; k < WAYS; k++) {
                    float zv = P[r][k]*wgt;
                    Zs[(NSUP + row)*WAYS + k] = zv;
                    g_Z[((size_t)b*NEXTN + NSUP + row)*WAYS + k] = zv;
                }
            }
        }
        if (lane < NSUP) {
            int y = ys[b*NSUP + lane];
            float v[5];
            #pragma unroll
            for (int k = 0; k < WAYS; k++) v[k] = (k == y) ? 1.0f : 0.0f;
            float e2 = entropy5(v);
            g_ent[b*NTOT + lane] = e2;
            float wgt = 1.0f - e2;
            #pragma unroll
            for (int k = 0; k < WAYS; k++) {
                float zv = v[k]*wgt;
                Zs[lane*WAYS + k] = zv;
                g_Z[((size_t)b*NEXTN + lane)*WAYS + k] = zv;
            }
        }
    }
    __syncthreads();
    if (t < WAYS) {
        float s = 0.f;
        for (int n = 0; n < NTOT; n++) s += Zs[n*WAYS + t];
        cs[t] = s;
    }
    __syncthreads();
    float acc[WAYS] = {0,0,0,0,0};
    // xs segment: rows 0..24, stride-DD pointer walk (no branches)
    {
        const float* fx = xs + (size_t)b*NSUP*DD + t;
        #pragma unroll 5
        for (int n = 0; n < NSUP; n++) {
            float f = fx[(size_t)n*DD];
            #pragma unroll
            for (int k = 0; k < WAYS; k++) acc[k] += Zs[n*WAYS + k]*f;
        }
    }
    // xq segment: rows 25..99
    {
        const float* fq = xq + (size_t)b*NQ*DD + t;
        #pragma unroll 5
        for (int n = 0; n < NQ; n++) {
            float f = fq[(size_t)n*DD];
            #pragma unroll
            for (int k = 0; k < WAYS; k++) acc[k] += Zs[(NSUP + n)*WAYS + k]*f;
        }
    }
    #pragma unroll
    for (int k = 0; k < WAYS; k++) {
        size_t pi = ((size_t)b*WAYS + k)*DD + t;
        float np = acc[k]/cs[k];
        g_proto[pi] = 0.4f*g_proto[pi] + 0.6f*np;
    }
}

// ------- fused: proto mask + add_proto + Z extension + sqn -------
__global__ void __launch_bounds__(256) k_mask_sqn(const float* __restrict__ xs,
                                                  const float* __restrict__ xq) {
    int b = blockIdx.x, t = threadIdx.x;   // 256 threads
    int w = t >> 5, lane = t & 31;
    __shared__ float nrm[5], dp[5][5], score[5], mk[5], omega_s;
    const float* pr = g_proto + (size_t)b*WAYS*DD;
    if (w < 5) {
        float a = 0.f;
        for (int d = lane; d < DD; d += 32) { float v = pr[w*DD + d]; a += v*v; }
        #pragma unroll
        for (int off = 16; off; off >>= 1) a += __shfl_xor_sync(0xffffffffu, a, off);
        if (lane == 0) nrm[w] = a;
    }
    __syncthreads();
    if (w < 5) {
        for (int j = 0; j < 5; j++) {
            float s = 0.f;
            for (int d = lane; d < DD; d += 32) s += pr[w*DD + d]*pr[j*DD + d];
            #pragma unroll
            for (int off = 16; off; off >>= 1) s += __shfl_xor_sync(0xffffffffu, s, off);
            if (lane == 0) {
                float d2 = fmaxf(nrm[w] + nrm[j] - 2.0f*s, 0.0f);
                dp[w][j] = expf(-10.0f*d2);
            }
        }
    }
    __syncthreads();
    if (t < 5) score[t] = entropy5(&dp[t][0]);
    if (w == 6) {
        float s = 0.f;
        for (int i = lane; i < NTOT; i += 32) s += g_ent[b*NTOT + i];
        #pragma unroll
        for (int off = 16; off; off >>= 1) s += __shfl_xor_sync(0xffffffffu, s, off);
        if (lane == 0) omega_s = s / 100.0f;
    }
    __syncthreads();
    if (t < 5) mk[t] = (score[t] < omega_s) ? 1.0f : 0.0f;
    __syncthreads();
    for (int idx = t; idx < WAYS*DD; idx += 256) {
        int i = idx / DD, d = idx % DD;
        g_addp[((size_t)b*WAYS + i)*DD + d] = pr[i*DD + d]*mk[i];
    }
    if (t < 25) {
        int i = t / 5, k = t % 5;
        g_Z[((size_t)b*NEXTN + NTOT + i)*WAYS + k] = dp[i][k]*mk[i];
    }
    __syncthreads();
    for (int row = w; row < NEXTN; row += 8) {
        const float* f = frow(xs, xq, b, row);
        float s = 0.f;
        for (int d = lane; d < DD; d += 32) { float v = f[d]; s += v*v; }
        #pragma unroll
        for (int off = 16; off; off >>= 1) s += __shfl_xor_sync(0xffffffffu, s, off);
        if (lane == 0) g_sqn[b*NEXTN + row] = s;
    }
}

// ------- 105x105 Gram -> W, kk x4 unroll with float4 smem loads -------
__global__ void __launch_bounds__(64) k_gram(const float* __restrict__ xs,
                                             const float* __restrict__ xq) {
    int b  = blockIdx.y;
    int ti = TIt[blockIdx.x], tj = TJt[blockIdx.x];
    int t  = threadIdx.x;             // 64 threads
    int tx = t & 7, ty = t >> 3;      // 8x8
    __shared__ float As[32][36], Bs[32][36];
    float acc[4][4] = {{0}};
    for (int dc = 0; dc < DD; dc += 32) {
        #pragma unroll
        for (int l = 0; l < 4; l++) {
            int id = t + l*64;              // 0..255
            int r = id >> 3, c4 = (id & 7)*4;
            int gi = ti*32 + r, gj = tj*32 + r;
            float4 av = make_float4(0,0,0,0), bv = make_float4(0,0,0,0);
            if (gi < NEXTN) av = *(const float4*)(frow(xs,xq,b,gi) + dc + c4);
            if (gj < NEXTN) bv = *(const float4*)(frow(xs,xq,b,gj) + dc + c4);
            *(float4*)&As[r][c4] = av;
            *(float4*)&Bs[r][c4] = bv;
        }
        __syncthreads();
        #pragma unroll
        for (int kk = 0; kk < 32; kk += 4) {
            float4 a4[4], b4[4];
            #pragma unroll
            for (int i = 0; i < 4; i++) a4[i] = *(const float4*)&As[ty*4+i][kk];
            #pragma unroll
            for (int j = 0; j < 4; j++) b4[j] = *(const float4*)&Bs[tx*4+j][kk];
            #pragma unroll
            for (int i = 0; i < 4; i++)
                #pragma unroll
                for (int j = 0; j < 4; j++)
                    acc[i][j] += a4[i].x*b4[j].x + a4[i].y*b4[j].y
                               + a4[i].z*b4[j].z + a4[i].w*b4[j].w;
        }
        __syncthreads();
    }
    size_t Wb = (size_t)b*NEXTN*NEXTN;
    #pragma unroll
    for (int ii = 0; ii < 4; ii++)
    #pragma unroll
    for (int jj = 0; jj < 4; jj++) {
        int i = ti*32 + ty*4 + ii, j = tj*32 + tx*4 + jj;
        if (i < NEXTN && j < NEXTN) {
            float d2 = g_sqn[b*NEXTN + i] + g_sqn[b*NEXTN + j] - 2.0f*acc[ii][jj];
            d2 = fmaxf(d2, 0.0f);
            float wv = (i == j) ? 0.0f : expf(-10.0f*d2);
            g_W[Wb + (size_t)i*NEXTN + j] = wv;
            if (ti != tj) g_W[Wb + (size_t)j*NEXTN + i] = wv;
        }
    }
}

// ------- solve (I - 0.7 Dm W Dm) X = Z -> g_M, + fused sink2 count -------
__global__ void __launch_bounds__(128) k_solve_count(const int* __restrict__ ys) {
    int b = blockIdx.x, t = threadIdx.x;
    int lane = t & 31;
    __shared__ float A[NEXTN*LDA];
    __shared__ float dm[NEXTN];
    const float* Wb = g_W + (size_t)b*NEXTN*NEXTN;
    for (int idx = t; idx < NEXTN*NEXTN; idx += 128) {
        int i = idx/NEXTN, j = idx%NEXTN;
        A[i*LDA + j] = Wb[idx];
    }
    __syncthreads();
    if (t < NEXTN) {
        float s = 0.f;
        for (int j = 0; j < NEXTN; j++) s += A[t*LDA + j];
        dm[t] = rsqrtf(s);
    }
    __syncthreads();
    if (t < NEXTN) {
        float di = 0.7f*dm[t];
        for (int j = 0; j < NEXTN; j++) {
            float v = di*dm[j]*A[t*LDA + j];
            A[t*LDA + j] = ((t == j) ? 1.0f : 0.0f) - v;
        }
        #pragma unroll
        for (int k = 0; k < WAYS; k++)
            A[t*LDA + NEXTN + k] = g_Z[((size_t)b*NEXTN + t)*WAYS + k];
    }
    __syncthreads();
    for (int k = 0; k < NEXTN; k++) {
        if (t < NEXTN && t != k) {
            float f = A[t*LDA + k] / A[k*LDA + k];
            int j = k + 1;
            if (j & 1) { A[t*LDA + j] -= f*A[k*LDA + j]; j++; }
            for (; j < NEXTN + WAYS; j += 2) {
                float2 pv = *(const float2*)&A[k*LDA + j];
                float2 av = *(float2*)&A[t*LDA + j];
                av.x -= f*pv.x; av.y -= f*pv.y;
                *(float2*)&A[t*LDA + j] = av;
            }
        }
        __syncthreads();
    }
    if (t < NEXTN) {
        float inv = 1.0f / A[t*LDA + t];
        #pragma unroll
        for (int k = 0; k < WAYS; k++)
            g_M[((size_t)b*NEXTN + t)*WAYS + k] = A[t*LDA + NEXTN + k]*inv;
    }
    // warp 0: sink2 count straight from shared
    if (t < 32) {
        float P[4][WAYS];
        #pragma unroll
        for (int r = 0; r < 4; r++) {
            int row = lane + 32*r;
            if (row < NEXTN) {
                float inv = 1.0f / A[row*LDA + row];
                #pragma unroll
                for (int k = 0; k < WAYS; k++) P[r][k] = A[row*LDA + NEXTN + k]*inv;
            } else {
                #pragma unroll
                for (int k = 0; k < WAYS; k++) P[r][k] = 0.f;
            }
        }
        int K = sink_iter<NEXTN, true>(P, b, lane, ys, 21.0f, -1);
        if (lane == 0) atomicMax(&g_it2, K);
    }
}

// ------- fused: sink2 replay + argmax predict -------
__global__ void k_sink2_pred(const int* __restrict__ ys, const int* __restrict__ yq,
                             float* __restrict__ out) {
    int gw = (blockIdx.x*blockDim.x + threadIdx.x) >> 5;
    int lane = threadIdx.x & 31;
    if (gw >= RUNS) return;
    int b = gw;
    float P[4][WAYS];
    const float* Mb = g_M + (size_t)b*NEXTN*WAYS;
    #pragma unroll
    for (int r = 0; r < 4; r++) {
        int row = lane + 32*r;
        #pragma unroll
        for (int k = 0; k < WAYS; k++) P[r][k] = (row < NEXTN) ? Mb[row*WAYS + k] : 0.f;
    }
    int T = g_it2;
    sink_iter<NEXTN, true>(P, b, lane, ys, 21.0f, T);
    int cnt = 0;
    #pragma unroll
    for (int r = 0; r < 4; r++) {
        int row = lane + 32*r;
        if (row >= NSUP && row < NTOT) {
            int am = 0; float bv = P[r][0];
            #pragma unroll
            for (int k = 1; k < 5; k++) { float v = P[r][k]; if (v > bv) { bv = v; am = k; } }
            cnt += (am == yq[b*NQ + (row - NSUP)]) ? 1 : 0;
        }
    }
    #pragma unroll
    for (int off = 16; off; off >>= 1) cnt += __shfl_xor_sync(0xffffffffu, cnt, off);
    if (lane == 0) out[b] = (float)cnt / 75.0f;
}

extern "C" void kernel_launch(void* const* d_in, const int* in_sizes, int n_in,
                              void* d_out, int out_size) {
    const float* xs = (const float*)d_in[0];
    const float* xq = (const float*)d_in[1];
    const int*   ys = (const int*)d_in[2];
    const int*   yq = (const int*)d_in[3];
    float* out = (float*)d_out;

    k_proto_init<<<RUNS, DD>>>(xs);
    for (int e = 0; e < 3; e++) {
        k_pq_count<<<RUNS, 256>>>(xq, e);
        k_apply_newproto<<<RUNS, DD>>>(ys, xs, xq, e);
        if (e == 2) {
            k_mask_sqn<<<RUNS, 256>>>(xs, xq);
            k_gram<<<dim3(10, RUNS), 64>>>(xs, xq);
            k_solve_count<<<RUNS, 128>>>(ys);
            k_sink2_pred<<<(RUNS*32 + 255)/256, 256>>>(ys, yq, out);
        }
    }
}